// round 17
// baseline (speedup 1.0000x reference)
#include <cuda_runtime.h>
typedef unsigned int u32; typedef unsigned long long u64; typedef unsigned short u16;
#define NB 64
#define NN 512
#define NF 64

__device__ float g_cs[NF];
__device__ __align__(16) u32  g_XWh [NB*NN*32];      // XW row-major f16x2 (diag adds)
__device__ __align__(16) uint4 g_XWfr[NB*8*4*8*32];  // [b][kt][qf][n][lane] f16 frags of XW (S-gemm B)
__device__ __align__(16) uint4 g_XTfr[NB*8*4*8*32];  // [b][kt][qk][n][lane] f16 frags of XW, k-dim=row
                                                     // (B operand of BOTH P-gemm and H-gemm)

__device__ __forceinline__ u32 smaddr(const void* p){
    u32 a; asm("{.reg .u64 t; cvta.to.shared.u64 t,%1; cvt.u32.u64 %0,t;}":"=r"(a):"l"(p)); return a;
}
__device__ __forceinline__ u32 cvt2h(float hi,float lo){ u32 r; asm("cvt.rn.f16x2.f32 %0,%1,%2;":"=r"(r):"f"(hi),"f"(lo)); return r; }
__device__ __forceinline__ float flo16(u32 p){ float f; asm("{.reg .b16 l,h; mov.b32 {l,h},%1; cvt.f32.f16 %0,l;}":"=f"(f):"r"(p)); return f; }
__device__ __forceinline__ float fhi16(u32 p){ float f; asm("{.reg .b16 l,h; mov.b32 {l,h},%1; cvt.f32.f16 %0,h;}":"=f"(f):"r"(p)); return f; }
__device__ __forceinline__ float tanhf_(float x){ float y; asm("tanh.approx.f32 %0,%1;":"=f"(y):"f"(x)); return y; }

#define MMAH(d,a,b0,b1) asm volatile( \
 "mma.sync.aligned.m16n8k16.row.col.f32.f16.f16.f32 {%0,%1,%2,%3},{%4,%5,%6,%7},{%8,%9},{%0,%1,%2,%3};" \
 : "+f"((d)[0]),"+f"((d)[1]),"+f"((d)[2]),"+f"((d)[3]) \
 : "r"((a)[0]),"r"((a)[1]),"r"((a)[2]),"r"((a)[3]),"r"(b0),"r"(b1))
#define CPA(dst,src) asm volatile("cp.async.cg.shared.global [%0],[%1],16;"::"r"(dst),"l"(src):"memory")
#define CPC() asm volatile("cp.async.commit_group;":::"memory")
#define CPW(n) asm volatile("cp.async.wait_group %0;"::"n"(n):"memory")

// ---------------------------------------------------------------------------
// XW = X@W per 64-row tile (f16 3-term MMA); col_sum(a) local -> g_cs; emit
// XW f16 row-major + 3-term fp16 k16 fragment packs (XWfr, XTfr).
__global__ __launch_bounds__(256) void k_prep(const float* __restrict__ X, const float* __restrict__ W,
                                              const float* __restrict__ am){
    __shared__ __align__(16) float Ws[64][64];
    __shared__ __align__(16) float Xs[64][68];
    __shared__ __align__(16) uint4 Wfr[4][8][32];
    __shared__ float csp[4][64];
    const int t=threadIdx.x, b=blockIdx.x>>3, kt=blockIdx.x&7, R0=blockIdx.x*64;
    const int w=t>>5, lane=t&31, g=lane>>2, tc=lane&3;
    {   // col_sum of a
        int f=t&63, seg=t>>6;
        float s=0.f;
        for(int i=seg;i<64;i+=4) s+=am[i*64+f];
        csp[seg][f]=s;
    }
    for(int i=t;i<64*64;i+=256) Ws[i>>6][i&63]=W[i];
    for(int i=t;i<64*64;i+=256) Xs[i>>6][i&63]=X[(size_t)(R0+(i>>6))*NF+(i&63)];
    __syncthreads();
    if(t<64) g_cs[t]=csp[0][t]+csp[1][t]+csp[2][t]+csp[3][t];
    // W B-fragments (f16 hi/lo, k16 chunks over input dim c)
    for(int u=t;u<1024;u+=256){
        int l2=u&31, n=(u>>5)&7, qc=u>>8;
        int gg=l2>>2, tcc=l2&3;
        int d=n*8+gg, c0=qc*16+2*tcc;
        float w0=Ws[c0][d], w1=Ws[c0+1][d], w2=Ws[c0+8][d], w3=Ws[c0+9][d];
        uint4 v;
        v.x=cvt2h(w1,w0); v.z=cvt2h(w1-fhi16(v.x), w0-flo16(v.x));
        v.y=cvt2h(w3,w2); v.w=cvt2h(w3-fhi16(v.y), w2-flo16(v.y));
        Wfr[qc][n][l2]=v;
    }
    __syncthreads();
    // XW = X@W via MMA: warp -> (m-frag w>>1, n-half w&1)
    const int mf=w>>1, nh=w&1;
    float acc[4][4]={};
#pragma unroll
    for(int qc=0;qc<4;qc++){
        float2 f0=*(float2*)&Xs[mf*16+g  ][qc*16+2*tc];
        float2 f1=*(float2*)&Xs[mf*16+g+8][qc*16+2*tc];
        float2 f2=*(float2*)&Xs[mf*16+g  ][qc*16+8+2*tc];
        float2 f3=*(float2*)&Xs[mf*16+g+8][qc*16+8+2*tc];
        u32 AH[4],AL[4];
        AH[0]=cvt2h(f0.y,f0.x); AL[0]=cvt2h(f0.y-fhi16(AH[0]), f0.x-flo16(AH[0]));
        AH[1]=cvt2h(f1.y,f1.x); AL[1]=cvt2h(f1.y-fhi16(AH[1]), f1.x-flo16(AH[1]));
        AH[2]=cvt2h(f2.y,f2.x); AL[2]=cvt2h(f2.y-fhi16(AH[2]), f2.x-flo16(AH[2]));
        AH[3]=cvt2h(f3.y,f3.x); AL[3]=cvt2h(f3.y-fhi16(AH[3]), f3.x-flo16(AH[3]));
#pragma unroll
        for(int nn=0;nn<4;nn++){
            uint4 v=Wfr[qc][nh*4+nn][lane];
            MMAH(acc[nn],AH,v.x,v.y);
            MMAH(acc[nn],AH,v.z,v.w);
            MMAH(acc[nn],AL,v.x,v.y);
        }
    }
    __syncthreads();   // all A-fragment reads of Xs done before overwrite
#pragma unroll
    for(int nn=0;nn<4;nn++){
        int d=(nh*4+nn)*8+2*tc;
        Xs[mf*16+g  ][d]=acc[nn][0]; Xs[mf*16+g  ][d+1]=acc[nn][1];
        Xs[mf*16+g+8][d]=acc[nn][2]; Xs[mf*16+g+8][d+1]=acc[nn][3];
    }
    __syncthreads();
    // XW f16 row-major (for diag adds in k_main)
#pragma unroll
    for(int u=0;u<8;u++){
        int idx=t+256*u; int r=idx>>5, c2=idx&31;
        g_XWh[(size_t)(R0+r)*32 + c2] = cvt2h(Xs[r][2*c2+1], Xs[r][2*c2]);
    }
    // XW frags (S-gemm B): col n*8+g = k row, chunk qf over f
#pragma unroll
    for(int u=0;u<4;u++){
        int idx=t+256*u; int n=(idx>>5)&7, qf=idx>>8;
        int k=n*8+g, f0=qf*16+2*tc;
        float x0=Xs[k][f0], x1=Xs[k][f0+1], x2=Xs[k][f0+8], x3=Xs[k][f0+9];
        uint4 v;
        v.x=cvt2h(x1,x0); v.z=cvt2h(x1-fhi16(v.x), x0-flo16(v.x));
        v.y=cvt2h(x3,x2); v.w=cvt2h(x3-fhi16(v.y), x2-flo16(v.y));
        g_XWfr[(((size_t)(b*8+kt)*4+qf)*8+n)*32+lane]=v;
    }
    // XT frags (P-gemm & H-gemm B): col n*8+g, chunk qk over rows
#pragma unroll
    for(int u=0;u<4;u++){
        int idx=t+256*u; int n=(idx>>5)&7, qk=idx>>8;
        int d=n*8+g, k0=qk*16+2*tc;
        float x0=Xs[k0][d], x1=Xs[k0+1][d], x2=Xs[k0+8][d], x3=Xs[k0+9][d];
        uint4 v;
        v.x=cvt2h(x1,x0); v.z=cvt2h(x1-fhi16(v.x), x0-flo16(v.x));
        v.y=cvt2h(x3,x2); v.w=cvt2h(x3-fhi16(v.y), x2-flo16(v.y));
        g_XTfr[(((size_t)(b*8+kt)*4+qk)*8+n)*32+lane]=v;
    }
}

// ---------------------------------------------------------------------------
// smem (bytes):
//  phase A: A0[0,18432) A1[18432,36864) Y0[36864,45056) Y1[45056,53248)
//  phase B overlay: buf0 XW@0 XT@16384 | buf1 XW@32768 XT@49152
//  rs@65536 (512) | bas@66048 (2048) | csm@68096 (256)  -> SMEMB 68352
#define SMEMB 68352
__global__ __launch_bounds__(256,2) void k_main(const float* __restrict__ A, const float* __restrict__ ba,
                                                const float* __restrict__ bW, float* __restrict__ H,
                                                const int* __restrict__ N32){
    extern __shared__ __align__(16) char sm[];
    float* rs =(float*)(sm+65536);
    float* bas=(float*)(sm+66048);
    float* csm=(float*)(sm+68096);
    const int t=threadIdx.x, w=t>>5, lane=t&31, g=lane>>2, tc=lane&3;
    const int b=blockIdx.y, i0=blockIdx.x*128;
    const u32 sbase=smaddr(sm);
    bas[t]=ba[t]; bas[256+t]=ba[256+t];
    if(t<64) csm[t]=g_cs[t];
    const int nb = (__ldg(&N32[1])!=0) ? __ldg(&N32[b]) : __ldg(&N32[2*b]);
    const float* Ab = A + ((size_t)b*NN+i0)*NN;

    auto issueA=[&](int p,int it){
        const int j0=it*32;
#pragma unroll
        for(int u=0;u<4;u++){
            int idx=t+256*u; int r=idx>>3, c=idx&7;
            CPA(sbase + p*18432 + (u32)(r*36+c*4)*4, Ab + (size_t)r*NN + j0 + c*4);
        }
        const uint4* src=g_XTfr + (size_t)(b*32+it*2)*256;   // == Y-frag source (unscaled)
#pragma unroll
        for(int u=0;u<2;u++){
            int idx=t+256*u;
            CPA(sbase + 36864 + p*8192 + (u32)idx*16, src+idx);
        }
        CPC();
    };

    // ---- phase A: pacc = A @ XW over K=512 (cs in epilogue); rowsum via ones-MMA ----
    float pacc[8][4]={};
    float racc[4]={};
    const u32 bones = (g==0) ? 0x3C003C00u : 0u;   // f16 ones in n-col 0
    issueA(0,0);
    for(int it=0; it<16; it++){
        const int p=it&1;
        CPW(0);
        __syncthreads();           // publishes buf p; proves buf p^1 drained
        if(it<15) issueA(p^1,it+1);
        const float* As=(const float*)(sm + p*18432);
        const char* Yb = sm + 36864 + p*8192;
#pragma unroll
        for(int cc=0;cc<2;cc++){
            float2 f0=*(const float2*)&As[(w*16+g  )*36+cc*16+2*tc];
            float2 f1=*(const float2*)&As[(w*16+g+8)*36+cc*16+2*tc];
            float2 f2=*(const float2*)&As[(w*16+g  )*36+cc*16+8+2*tc];
            float2 f3=*(const float2*)&As[(w*16+g+8)*36+cc*16+8+2*tc];
            u32 AH[4],AL[4];
            AH[0]=cvt2h(f0.y,f0.x); AL[0]=cvt2h(f0.y-fhi16(AH[0]), f0.x-flo16(AH[0]));
            AH[1]=cvt2h(f1.y,f1.x); AL[1]=cvt2h(f1.y-fhi16(AH[1]), f1.x-flo16(AH[1]));
            AH[2]=cvt2h(f2.y,f2.x); AL[2]=cvt2h(f2.y-fhi16(AH[2]), f2.x-flo16(AH[2]));
            AH[3]=cvt2h(f3.y,f3.x); AL[3]=cvt2h(f3.y-fhi16(AH[3]), f3.x-flo16(AH[3]));
            const uint4* yb=(const uint4*)(Yb + cc*4096) + lane;
#pragma unroll
            for(int n=0;n<8;n++){
                uint4 v=yb[n*32];
                MMAH(pacc[n],AH,v.x,v.y);
                MMAH(pacc[n],AH,v.z,v.w);
                MMAH(pacc[n],AL,v.x,v.y);
            }
            MMAH(racc,AH,bones,bones);
            MMAH(racc,AL,bones,bones);
        }
    }
    if(tc==0){   // rowsum result lives in n-col 0 => lanes tc==0
        const int il=i0+w*16+g;
        rs[w*16+g]   = racc[0] + ((il  )<nb ? 1.f : 0.f);
        rs[w*16+g+8] = racc[2] + ((il+8)<nb ? 1.f : 0.f);
    }
    __syncthreads();   // phase-A buffers fully drained before phase-B prefetch

    // ---- prefetch phase-B kt=0 into buf0 ----
    {
        const uint4* sw=g_XWfr + (size_t)(b*8)*1024;
        const uint4* st=g_XTfr + (size_t)(b*8)*1024;
#pragma unroll
        for(int u=0;u<4;u++){ int idx=t+256*u; CPA(sbase+(u32)idx*16, sw+idx); }
#pragma unroll
        for(int u=0;u<4;u++){ int idx=t+256*u; CPA(sbase+16384+(u32)idx*16, st+idx); }
        CPC();
    }

    // ---- diag add + cs scale; P hi-frags -> registers only ----
    u32 PHr[4][4];
    {
        const int il=i0+w*16+g, ih=il+8;
#pragma unroll
        for(int n=0;n<8;n++){
            const int f=n*8+2*tc;
            float d0=0.f,d1=0.f,e0=0.f,e1=0.f;
            if(il<nb){ u32 p=g_XWh[(size_t)(b*NN+il)*32 + n*4+tc]; d0=flo16(p); d1=fhi16(p); }
            if(ih<nb){ u32 p=g_XWh[(size_t)(b*NN+ih)*32 + n*4+tc]; e0=flo16(p); e1=fhi16(p); }
            const float c0=csm[f], c1=csm[f+1];
            float p0=(pacc[n][0]+d0)*c0, p1=(pacc[n][1]+d1)*c1;
            float p2=(pacc[n][2]+e0)*c0, p3=(pacc[n][3]+e1)*c1;
            PHr[n>>1][(n&1)?2:0]=cvt2h(p1,p0);
            PHr[n>>1][(n&1)?3:1]=cvt2h(p3,p2);
        }
    }

    // ---- phase B: S = tanh(P@XW^T + r*ba); H += S@XW (hi-only P & S, dbl-buffered) ----
    float hacc[8][4]={};
    float rv0=0.f, rv1=0.f;
    for(int kt=0;kt<8;kt++){
        const int p=kt&1;
        CPW(0);
        __syncthreads();           // publishes buf p (+ rs at kt=0); buf p^1 drained
        if(kt==0){ rv0=rs[w*16+g]; rv1=rs[w*16+g+8]; }
        if(kt<7){
            const uint4* sw=g_XWfr + (size_t)(b*8+kt+1)*1024;
            const uint4* st=g_XTfr + (size_t)(b*8+kt+1)*1024;
            const u32 dst=sbase+(u32)(p^1)*32768;
#pragma unroll
            for(int u=0;u<4;u++){ int idx=t+256*u; CPA(dst+(u32)idx*16, sw+idx); }
#pragma unroll
            for(int u=0;u<4;u++){ int idx=t+256*u; CPA(dst+16384+(u32)idx*16, st+idx); }
            CPC();
        }
        const uint4* XWfs=(const uint4*)(sm + p*32768);
        const uint4* XTfs=(const uint4*)(sm + p*32768 + 16384);
        float sacc[8][4]={};
#pragma unroll
        for(int qf=0;qf<4;qf++){
            const uint4* wb=XWfs + qf*256 + lane;
#pragma unroll
            for(int n=0;n<8;n++){
                uint4 v=wb[n*32];
                MMAH(sacc[n],PHr[qf],v.x,v.y);
                MMAH(sacc[n],PHr[qf],v.z,v.w);
            }
        }
#pragma unroll
        for(int qk=0;qk<4;qk++){
            u32 Sh[4];
#pragma unroll
            for(int qq=0;qq<2;qq++){
                const int n=2*qk+qq;
                const int kc=kt*64+n*8+2*tc;
                const float b0v=bas[kc], b1v=bas[kc+1];
                float s0=tanhf_(sacc[n][0]+rv0*b0v);
                float s1=tanhf_(sacc[n][1]+rv0*b1v);
                float s2=tanhf_(sacc[n][2]+rv1*b0v);
                float s3=tanhf_(sacc[n][3]+rv1*b1v);
                Sh[2*qq]  =cvt2h(s1,s0);
                Sh[2*qq+1]=cvt2h(s3,s2);
            }
            const uint4* tb=XTfs + qk*256 + lane;
#pragma unroll
            for(int n=0;n<8;n++){
                uint4 v=tb[n*32];
                MMAH(hacc[n],Sh,v.x,v.y);
                MMAH(hacc[n],Sh,v.z,v.w);
            }
        }
    }

    // ---- epilogue ----
    {
        const int il=i0+w*16+g, ih=il+8;
#pragma unroll
        for(int n=0;n<8;n++){
            const int d=n*8+2*tc;
            float2 v0, v1;
            v0.x=hacc[n][0]+bW[d]; v0.y=hacc[n][1]+bW[d+1];
            v1.x=hacc[n][2]+bW[d]; v1.y=hacc[n][3]+bW[d+1];
            *(float2*)&H[((size_t)b*NN+il)*NF+d]=v0;
            *(float2*)&H[((size_t)b*NN+ih)*NF+d]=v1;
        }
    }
}

// ---------------------------------------------------------------------------
extern "C" void kernel_launch(void* const* d_in, const int* in_sizes, int n_in,
                              void* d_out, int out_size){
    const float* X =(const float*)d_in[0];
    const float* A =(const float*)d_in[1];
    const int*   N =(const int*)d_in[2];
    const float* W =(const float*)d_in[3];
    const float* a =(const float*)d_in[4];
    const float* bW=(const float*)d_in[5];
    const float* ba=(const float*)d_in[6];
    float* H=(float*)d_out;
    cudaFuncSetAttribute(k_main, cudaFuncAttributeMaxDynamicSharedMemorySize, SMEMB);
    k_prep<<<NB*8,256>>>(X,W,a);
    k_main<<<dim3(4,NB),256,SMEMB>>>(A,ba,bW,H,N);
}